// round 10
// baseline (speedup 1.0000x reference)
#include <cuda_runtime.h>
#include <cuda_bf16.h>

#define N_PP 8192
#define DIM  16
#define L2E  1.4426950408889634f

#define TPB      256
#define ROWS_PT  128                 // rows per pair tile
#define COLS_PT  512                 // cols per pair tile (2/thread)
#define NB_ROW   (N_PP / ROWS_PT)    // 64
#define NB_COL   (N_PP / COLS_PT)    // 16
#define N_PP_ACT 544                 // active pp tiles
#define N_AP_T   (NB_ROW * NB_COL)   // 1024
#define N_EDGE_T 104
#define NB_TOTAL (N_PP_ACT + N_AP_T + N_EDGE_T)   // 1672

// accumulators: 0 = nonlink_pp, 1 = link_pp, 2 = nonlink_ap, 3 = link_ap
__device__ double g_acc[4];
__device__ unsigned int g_arrive;

typedef unsigned long long ull;

__device__ __forceinline__ float fast_sqrt(float x) {
    float r; asm("sqrt.approx.f32 %0, %1;" : "=f"(r) : "f"(x)); return r;
}
__device__ __forceinline__ float fast_exp2(float x) {
    float r; asm("ex2.approx.f32 %0, %1;" : "=f"(r) : "f"(x)); return r;
}
__device__ __forceinline__ ull pack2(float lo, float hi) {
    ull r; asm("mov.b64 %0, {%1, %2};" : "=l"(r) : "f"(lo), "f"(hi)); return r;
}
__device__ __forceinline__ void unpack2(ull v, float& lo, float& hi) {
    asm("mov.b64 {%0, %1}, %2;" : "=f"(lo), "=f"(hi) : "l"(v));
}
__device__ __forceinline__ ull fma2(ull a, ull b, ull c) {
    ull d; asm("fma.rn.f32x2 %0, %1, %2, %3;" : "=l"(d) : "l"(a), "l"(b), "l"(c));
    return d;
}
__device__ __forceinline__ ull add2(ull a, ull b) {
    ull d; asm("add.rn.f32x2 %0, %1, %2;" : "=l"(d) : "l"(a), "l"(b));
    return d;
}

__device__ __forceinline__ float block_reduce(float v, float* sh) {
    #pragma unroll
    for (int off = 16; off > 0; off >>= 1)
        v += __shfl_down_sync(0xffffffffu, v, off);
    int lane = threadIdx.x & 31;
    int w = threadIdx.x >> 5;
    if (lane == 0) sh[w] = v;
    __syncthreads();
    if (w == 0) {
        v = (lane < (int)(TPB >> 5)) ? sh[lane] : 0.f;
        #pragma unroll
        for (int off = 4; off > 0; off >>= 1)
            v += __shfl_down_sync(0xffffffffu, v, off);
    }
    return v;
}

template <bool MASKED>
__device__ __forceinline__ void pair_loop(
    const ulonglong2* __restrict__ xs,   // ROWS_PT x 4 (packed -2x)
    const float2* __restrict__ xmeta,    // (xn, lrow*L2E)
    const ull y0[8], const ull y1[8],
    float yn0, float yn1,
    int row0, int j0g, int j1g,
    float& acc0, float& acc1)
{
    const ull zz = pack2(0.f, 0.f);
    #pragma unroll 2
    for (int rr = 0; rr < ROWS_PT; rr++) {
        const ulonglong2* xr = xs + rr * 4;
        ulonglong2 p0 = xr[0], p1 = xr[1], p2 = xr[2], p3 = xr[3];
        float2 m = xmeta[rr];
        // split 8-deep chains into 2x4 for ILP
        ull c0a = pack2(m.x, yn0);
        ull c1a = pack2(m.x, yn1);
        ull c0b = zz;
        ull c1b = zz;
        c0a = fma2(p0.x, y0[0], c0a);  c1a = fma2(p0.x, y1[0], c1a);
        c0b = fma2(p2.x, y0[4], c0b);  c1b = fma2(p2.x, y1[4], c1b);
        c0a = fma2(p0.y, y0[1], c0a);  c1a = fma2(p0.y, y1[1], c1a);
        c0b = fma2(p2.y, y0[5], c0b);  c1b = fma2(p2.y, y1[5], c1b);
        c0a = fma2(p1.x, y0[2], c0a);  c1a = fma2(p1.x, y1[2], c1a);
        c0b = fma2(p3.x, y0[6], c0b);  c1b = fma2(p3.x, y1[6], c1b);
        c0a = fma2(p1.y, y0[3], c0a);  c1a = fma2(p1.y, y1[3], c1a);
        c0b = fma2(p3.y, y0[7], c0b);  c1b = fma2(p3.y, y1[7], c1b);
        ull c0 = add2(c0a, c0b);
        ull c1 = add2(c1a, c1b);
        float a0, a1, b0, b1;
        unpack2(c0, a0, a1); unpack2(c1, b0, b1);
        float d2_0 = fabsf(a0 + a1);
        float d2_1 = fabsf(b0 + b1);
        float t0 = fast_exp2(fmaf(fast_sqrt(d2_0), -L2E, m.y));
        float t1 = fast_exp2(fmaf(fast_sqrt(d2_1), -L2E, m.y));
        if (MASKED) {
            int r = row0 + rr;
            if (j0g <= r) t0 = 0.f;
            if (j1g <= r) t1 = 0.f;
        }
        acc0 += t0;
        acc1 += t1;
    }
}

__global__ __launch_bounds__(TPB, 4) void fused_kernel(
    const float* __restrict__ p_star,
    const float* __restrict__ p,
    const float* __restrict__ a,
    const float* __restrict__ beta,
    const float* __restrict__ gamma,
    const int* __restrict__ e_pp,
    const int* __restrict__ e_ap,
    int E,
    float* __restrict__ out)
{
    __shared__ ulonglong2 xs[ROWS_PT * 4];   // 8KB
    __shared__ float2     xmeta[ROWS_PT];    // 1KB
    __shared__ float      red[8];

    const int bid = blockIdx.x;
    const int tid = threadIdx.x;

    if (bid < N_PP_ACT + N_AP_T) {
        // ---------------- pair tile ----------------
        const bool is_pp = (bid < N_PP_ACT);
        int rb, cb;
        if (is_pp) {
            int t = bid;
            int g = 0;
            #pragma unroll
            for (int i = 0; i < 16; i++) {
                int cnt = 4 * (16 - i);
                if (t < cnt) { g = i; break; }
                t -= cnt;
            }
            int w = 16 - g;
            rb = g * 4 + t / w;
            cb = g + t % w;
        } else {
            int t = bid - N_PP_ACT;
            rb = t >> 4;
            cb = t & 15;
        }
        const int row0 = rb * ROWS_PT;
        const int col0 = cb * COLS_PT;

        // stage row tile (threads 0..127)
        if (tid < ROWS_PT) {
            int r = row0 + tid;
            const float4* xr = reinterpret_cast<const float4*>(p_star + (size_t)r * DIM);
            float4 v0 = xr[0], v1 = xr[1], v2 = xr[2], v3 = xr[3];
            float xn =
                v0.x*v0.x + v0.y*v0.y + v0.z*v0.z + v0.w*v0.w +
                v1.x*v1.x + v1.y*v1.y + v1.z*v1.z + v1.w*v1.w +
                v2.x*v2.x + v2.y*v2.y + v2.z*v2.z + v2.w*v2.w +
                v3.x*v3.x + v3.y*v3.y + v3.z*v3.z + v3.w*v3.w;
            ulonglong2* xd = xs + tid * 4;
            xd[0] = make_ulonglong2(pack2(-2.f*v0.x, -2.f*v0.y),
                                    pack2(-2.f*v0.z, -2.f*v0.w));
            xd[1] = make_ulonglong2(pack2(-2.f*v1.x, -2.f*v1.y),
                                    pack2(-2.f*v1.z, -2.f*v1.w));
            xd[2] = make_ulonglong2(pack2(-2.f*v2.x, -2.f*v2.y),
                                    pack2(-2.f*v2.z, -2.f*v2.w));
            xd[3] = make_ulonglong2(pack2(-2.f*v3.x, -2.f*v3.y),
                                    pack2(-2.f*v3.z, -2.f*v3.w));
            float wrow = is_pp ? gamma[r] : beta[r];
            xmeta[tid] = make_float2(xn, wrow * L2E);
        }
        __syncthreads();

        // this thread's two columns
        const int j0 = col0 + 2 * tid;
        const int j1 = j0 + 1;
        const float* ysrc = is_pp ? p : a;
        ull y0[8], y1[8];
        float yn0 = 0.f, yn1 = 0.f;
        {
            const float4* ya = reinterpret_cast<const float4*>(ysrc + (size_t)j0 * DIM);
            #pragma unroll
            for (int k = 0; k < 4; k++) {
                float4 v = ya[k];
                y0[2*k]   = pack2(v.x, v.y);
                y0[2*k+1] = pack2(v.z, v.w);
                yn0 += v.x*v.x + v.y*v.y + v.z*v.z + v.w*v.w;
            }
            const float4* yb = reinterpret_cast<const float4*>(ysrc + (size_t)j1 * DIM);
            #pragma unroll
            for (int k = 0; k < 4; k++) {
                float4 v = yb[k];
                y1[2*k]   = pack2(v.x, v.y);
                y1[2*k+1] = pack2(v.z, v.w);
                yn1 += v.x*v.x + v.y*v.y + v.z*v.z + v.w*v.w;
            }
        }

        float acc0 = 0.f, acc1 = 0.f;
        const bool straddle = is_pp && (col0 < row0 + ROWS_PT);
        if (straddle)
            pair_loop<true >(xs, xmeta, y0, y1, yn0, yn1, row0, j0, j1, acc0, acc1);
        else
            pair_loop<false>(xs, xmeta, y0, y1, yn0, yn1, row0, j0, j1, acc0, acc1);

        const float* wcol = is_pp ? gamma : beta;
        acc0 *= fast_exp2(wcol[N_PP + j0] * L2E);
        acc1 *= fast_exp2(wcol[N_PP + j1] * L2E);

        float bsum = block_reduce(acc0 + acc1, red);
        if (tid == 0)
            atomicAdd(&g_acc[is_pp ? 0 : 2], (double)bsum);
    } else {
        // ---------------- edge stripe ----------------
        const int eb = bid - (N_PP_ACT + N_AP_T);
        float acc_pp = 0.f, acc_ap = 0.f;
        for (int e = eb * TPB + tid; e < E; e += N_EDGE_T * TPB) {
            {
                int s = e_pp[e];
                int t = e_pp[E + e];
                const float4* xsrc = reinterpret_cast<const float4*>(p_star + (size_t)s * DIM);
                const float4* yt = reinterpret_cast<const float4*>(p + (size_t)t * DIM);
                float d2 = 0.f;
                #pragma unroll
                for (int k = 0; k < 4; k++) {
                    float4 xv = xsrc[k], yv = yt[k];
                    float dx = xv.x - yv.x, dy = xv.y - yv.y;
                    float dz = xv.z - yv.z, dw = xv.w - yv.w;
                    d2 += dx*dx + dy*dy + dz*dz + dw*dw;
                }
                acc_pp += gamma[s] + gamma[t + N_PP] - fast_sqrt(d2);
            }
            {
                int s = e_ap[e];
                int t = e_ap[E + e];            // in [N_PP, 2*N_PP)
                const float4* xsrc = reinterpret_cast<const float4*>(p_star + (size_t)s * DIM);
                const float4* yt = reinterpret_cast<const float4*>(a + (size_t)(t - N_PP) * DIM);
                float d2 = 0.f;
                #pragma unroll
                for (int k = 0; k < 4; k++) {
                    float4 xv = xsrc[k], yv = yt[k];
                    float dx = xv.x - yv.x, dy = xv.y - yv.y;
                    float dz = xv.z - yv.z, dw = xv.w - yv.w;
                    d2 += dx*dx + dy*dy + dz*dz + dw*dw;
                }
                acc_ap += beta[s] + beta[t] - fast_sqrt(d2);
            }
        }
        float s_pp = block_reduce(acc_pp, red);
        __syncthreads();
        float s_ap = block_reduce(acc_ap, red);
        if (tid == 0) {
            atomicAdd(&g_acc[1], (double)s_pp);
            atomicAdd(&g_acc[3], (double)s_ap);
        }
    }

    // ---------------- arrival + finalize ----------------
    __syncthreads();
    if (tid == 0) {
        __threadfence();
        unsigned old = atomicAdd(&g_arrive, 1u);
        if (old == (unsigned)(NB_TOTAL - 1)) {
            double nll_pp = -(g_acc[1] - g_acc[0]);
            double nll_ap = -(g_acc[3] - g_acc[2]);
            out[0] = (float)(0.5 * nll_pp / (double)N_PP + 0.5 * nll_ap / (double)N_PP);
            g_acc[0] = 0.0; g_acc[1] = 0.0; g_acc[2] = 0.0; g_acc[3] = 0.0;
            g_arrive = 0u;
            __threadfence();
        }
    }
}

extern "C" void kernel_launch(void* const* d_in, const int* in_sizes, int n_in,
                              void* d_out, int out_size) {
    const float* p_star = (const float*)d_in[0];
    const float* p      = (const float*)d_in[1];
    const float* a      = (const float*)d_in[2];
    const float* beta   = (const float*)d_in[3];
    const float* gamma  = (const float*)d_in[4];
    const int*   e_pp   = (const int*)d_in[5];
    const int*   e_ap   = (const int*)d_in[6];
    int E = in_sizes[5] / 2;

    fused_kernel<<<NB_TOTAL, TPB>>>(p_star, p, a, beta, gamma,
                                    e_pp, e_ap, E, (float*)d_out);
}

// round 12
// speedup vs baseline: 1.1946x; 1.1946x over previous
#include <cuda_runtime.h>
#include <cuda_bf16.h>
#include <cstdint>

#define N_PP 8192
#define DIM  16
#define L2E  1.4426950408889634f

#define TPB      256
#define ROWS_PT  128                 // rows per pair tile (8 warps x 16)
#define COLS_PT  512                 // cols per pair tile (64 n8 subtiles)
#define NB_ROW   (N_PP / ROWS_PT)    // 64
#define NB_COL   (N_PP / COLS_PT)    // 16
#define N_PP_ACT 544                 // active pp tiles
#define N_AP_T   (NB_ROW * NB_COL)   // 1024
#define N_EDGE_T 104
#define NB_TOTAL (N_PP_ACT + N_AP_T + N_EDGE_T)   // 1672

// row record: 80B = [hi bf16 x16 | lo bf16 x16 | meta float4] as 5 x uint4
#define REC 5
// smem layout (dynamic)
#define SM_A   0                      // 128 rows x 80B = 10240
#define SM_B   (128 * 80)             // 512 rows x 80B = 40960
#define SM_RED (SM_B + 512 * 80)      // 51200
#define SMEM_TOTAL (SM_RED + 64)

__device__ uint4 g_U[8192 * REC];     // p_star rows: -2x, meta (xn, gamma*L2E, beta*L2E)
__device__ uint4 g_V[16384 * REC];    // p then a rows: y, meta (yn, lw*L2E)
__device__ double g_acc[4];           // 0=nonlink_pp 1=link_pp 2=nonlink_ap 3=link_ap
__device__ unsigned int g_arrive;

__device__ __forceinline__ float fast_sqrt(float x) {
    float r; asm("sqrt.approx.f32 %0, %1;" : "=f"(r) : "f"(x)); return r;
}
__device__ __forceinline__ float fast_exp2(float x) {
    float r; asm("ex2.approx.f32 %0, %1;" : "=f"(r) : "f"(x)); return r;
}
__device__ __forceinline__ uint32_t smem_u32(const void* p) {
    uint32_t r;
    asm("{ .reg .u64 t; cvta.to.shared.u64 t, %1; cvt.u32.u64 %0, t; }" : "=r"(r) : "l"(p));
    return r;
}
__device__ __forceinline__ void ldsm_x4(uint32_t* d, uint32_t addr) {
    asm volatile("ldmatrix.sync.aligned.m8n8.x4.shared.b16 {%0,%1,%2,%3}, [%4];"
                 : "=r"(d[0]), "=r"(d[1]), "=r"(d[2]), "=r"(d[3]) : "r"(addr));
}
__device__ __forceinline__ void ldsm_x2(uint32_t* d, uint32_t addr) {
    asm volatile("ldmatrix.sync.aligned.m8n8.x2.shared.b16 {%0,%1}, [%2];"
                 : "=r"(d[0]), "=r"(d[1]) : "r"(addr));
}
__device__ __forceinline__ void mma_bf16(float* c, const uint32_t* a, const uint32_t* b) {
    asm volatile(
        "mma.sync.aligned.m16n8k16.row.col.f32.bf16.bf16.f32 "
        "{%0,%1,%2,%3}, {%4,%5,%6,%7}, {%8,%9}, {%0,%1,%2,%3};"
        : "+f"(c[0]), "+f"(c[1]), "+f"(c[2]), "+f"(c[3])
        : "r"(a[0]), "r"(a[1]), "r"(a[2]), "r"(a[3]), "r"(b[0]), "r"(b[1]));
}

__device__ __forceinline__ float block_reduce(float v, float* sh) {
    #pragma unroll
    for (int off = 16; off > 0; off >>= 1)
        v += __shfl_down_sync(0xffffffffu, v, off);
    int lane = threadIdx.x & 31;
    int w = threadIdx.x >> 5;
    if (lane == 0) sh[w] = v;
    __syncthreads();
    if (w == 0) {
        v = (lane < (int)(TPB >> 5)) ? sh[lane] : 0.f;
        #pragma unroll
        for (int off = 4; off > 0; off >>= 1)
            v += __shfl_down_sync(0xffffffffu, v, off);
    }
    return v;
}

// ---------------- prep: build packed hi/lo row records ----------------
__device__ __forceinline__ void pack_rec(uint4* dst, const float* vals, float4 meta) {
    uint16_t hb[16], lb[16];
    #pragma unroll
    for (int k = 0; k < 16; k++) {
        __nv_bfloat16 h = __float2bfloat16(vals[k]);
        __nv_bfloat16 l = __float2bfloat16(vals[k] - __bfloat162float(h));
        hb[k] = *reinterpret_cast<uint16_t*>(&h);
        lb[k] = *reinterpret_cast<uint16_t*>(&l);
    }
    uint32_t w[8];
    #pragma unroll
    for (int k = 0; k < 8; k++) w[k] = (uint32_t)hb[2*k] | ((uint32_t)hb[2*k+1] << 16);
    dst[0] = make_uint4(w[0], w[1], w[2], w[3]);
    dst[1] = make_uint4(w[4], w[5], w[6], w[7]);
    #pragma unroll
    for (int k = 0; k < 8; k++) w[k] = (uint32_t)lb[2*k] | ((uint32_t)lb[2*k+1] << 16);
    dst[2] = make_uint4(w[0], w[1], w[2], w[3]);
    dst[3] = make_uint4(w[4], w[5], w[6], w[7]);
    dst[4] = make_uint4(__float_as_uint(meta.x), __float_as_uint(meta.y),
                        __float_as_uint(meta.z), __float_as_uint(meta.w));
}

__global__ void prep_kernel(const float* __restrict__ p_star,
                            const float* __restrict__ p,
                            const float* __restrict__ a,
                            const float* __restrict__ beta,
                            const float* __restrict__ gamma) {
    int idx = blockIdx.x * 256 + threadIdx.x;
    float vals[16];
    if (idx < 8192) {
        const float* x = p_star + (size_t)idx * DIM;
        float xn = 0.f;
        #pragma unroll
        for (int k = 0; k < DIM; k++) { float v = x[k]; xn += v*v; vals[k] = -2.f*v; }
        pack_rec(g_U + (size_t)idx * REC, vals,
                 make_float4(xn, gamma[idx] * L2E, beta[idx] * L2E, 0.f));
    } else if (idx < 24576) {
        int j = idx - 8192;                  // 0..16383: p cols then a cols
        const float* y = (j < N_PP) ? (p + (size_t)j * DIM) : (a + (size_t)(j - N_PP) * DIM);
        float yn = 0.f;
        #pragma unroll
        for (int k = 0; k < DIM; k++) { float v = y[k]; yn += v*v; vals[k] = v; }
        float lw = (j < N_PP) ? gamma[N_PP + j] : beta[j];
        pack_rec(g_V + (size_t)j * REC, vals, make_float4(yn, lw * L2E, 0.f, 0.f));
    }
}

// ---------------- fused: HMMA pair tiles + edge stripes + finalize ----------------
template <bool MASKED>
__device__ __forceinline__ float tile_body(
    char* smem, uint32_t sbase, bool is_pp, int row0, int col0)
{
    const int tid = threadIdx.x;
    const int lane = tid & 31;
    const int w = tid >> 5;

    // A fragments (per-warp 16 rows), hi and lo
    uint32_t ah[4], al[4];
    {
        uint32_t aaddr = sbase + SM_A + (uint32_t)(w * 16 + (lane & 15)) * 80
                       + ((uint32_t)(lane >> 4) << 4);
        ldsm_x4(ah, aaddr);
        ldsm_x4(al, aaddr + 32);
    }
    // row meta (hoisted): rows r_lo = w*16 + lane/4, r_hi = +8
    const int rl = w * 16 + (lane >> 2);
    float4 mlo = *reinterpret_cast<float4*>(smem + SM_A + rl * 80 + 64);
    float4 mhi = *reinterpret_cast<float4*>(smem + SM_A + (rl + 8) * 80 + 64);
    const float xn_lo = mlo.x, xn_hi = mhi.x;
    const float wr_lo = is_pp ? mlo.y : mlo.z;
    const float wr_hi = is_pp ? mhi.y : mhi.z;
    const int rg_lo = row0 + rl, rg_hi = rg_lo + 8;

    float acc = 0.f;
    #pragma unroll 2
    for (int ct = 0; ct < COLS_PT / 8; ct++) {
        const int j0 = ct * 8;
        uint32_t bh[2], bl[2];
        uint32_t baddr = sbase + SM_B + (uint32_t)(j0 + (lane & 7)) * 80
                       + ((uint32_t)((lane >> 3) & 1) << 4);
        ldsm_x2(bh, baddr);
        ldsm_x2(bl, baddr + 32);

        float c[4] = {0.f, 0.f, 0.f, 0.f};
        mma_bf16(c, ah, bh);   // hi*hi
        mma_bf16(c, ah, bl);   // hi*lo
        mma_bf16(c, al, bh);   // lo*hi

        const int ca = j0 + ((lane & 3) << 1);
        float2 ma = *reinterpret_cast<float2*>(smem + SM_B + ca * 80 + 64);       // (yn, lw)
        float2 mb = *reinterpret_cast<float2*>(smem + SM_B + (ca + 1) * 80 + 64);

        // per-(r,c) constants
        float n00 = xn_lo + ma.x, n01 = xn_lo + mb.x;
        float n10 = xn_hi + ma.x, n11 = xn_hi + mb.x;
        float w00 = wr_lo + ma.y, w01 = wr_lo + mb.y;
        float w10 = wr_hi + ma.y, w11 = wr_hi + mb.y;

        float t0 = fast_exp2(fmaf(fast_sqrt(fabsf(c[0] + n00)), -L2E, w00));
        float t1 = fast_exp2(fmaf(fast_sqrt(fabsf(c[1] + n01)), -L2E, w01));
        float t2 = fast_exp2(fmaf(fast_sqrt(fabsf(c[2] + n10)), -L2E, w10));
        float t3 = fast_exp2(fmaf(fast_sqrt(fabsf(c[3] + n11)), -L2E, w11));
        if (MASKED) {
            int ja = col0 + ca, jb = ja + 1;
            if (ja <= rg_lo) t0 = 0.f;
            if (jb <= rg_lo) t1 = 0.f;
            if (ja <= rg_hi) t2 = 0.f;
            if (jb <= rg_hi) t3 = 0.f;
        }
        acc += (t0 + t1) + (t2 + t3);
    }
    return acc;
}

__global__ __launch_bounds__(TPB, 4) void fused_kernel(
    const float* __restrict__ p_star,
    const float* __restrict__ p,
    const float* __restrict__ a,
    const float* __restrict__ beta,
    const float* __restrict__ gamma,
    const int* __restrict__ e_pp,
    const int* __restrict__ e_ap,
    int E,
    float* __restrict__ out)
{
    extern __shared__ char smem[];
    const uint32_t sbase = smem_u32(smem);
    float* red = reinterpret_cast<float*>(smem + SM_RED);
    const int bid = blockIdx.x;
    const int tid = threadIdx.x;

    if (bid < N_PP_ACT + N_AP_T) {
        // ---------------- pair tile ----------------
        const bool is_pp = (bid < N_PP_ACT);
        int rb, cb;
        if (is_pp) {
            int t = bid;
            int g = 0;
            #pragma unroll
            for (int i = 0; i < 16; i++) {
                int cnt = 4 * (16 - i);
                if (t < cnt) { g = i; break; }
                t -= cnt;
            }
            int wd = 16 - g;
            rb = g * 4 + t / wd;
            cb = g + t % wd;
        } else {
            int t = bid - N_PP_ACT;
            rb = t >> 4;
            cb = t & 15;
        }
        const int row0 = rb * ROWS_PT;
        const int col0 = cb * COLS_PT;
        const int vbase = (is_pp ? 0 : N_PP) + col0;   // g_V row base

        // stage A rows (128 x 5 uint4)
        {
            const uint4* src = g_U + (size_t)row0 * REC;
            for (int idx = tid; idx < ROWS_PT * REC; idx += TPB) {
                int row = idx / REC, q = idx % REC;
                *reinterpret_cast<uint4*>(smem + SM_A + row * 80 + q * 16) = src[idx];
            }
        }
        // stage B rows (512 x 5 uint4)
        {
            const uint4* src = g_V + (size_t)vbase * REC;
            for (int idx = tid; idx < COLS_PT * REC; idx += TPB) {
                int row = idx / REC, q = idx % REC;
                *reinterpret_cast<uint4*>(smem + SM_B + row * 80 + q * 16) = src[idx];
            }
        }
        __syncthreads();

        const bool straddle = is_pp && (cb == (rb >> 2));
        float acc = straddle
            ? tile_body<true >(smem, sbase, is_pp, row0, col0)
            : tile_body<false>(smem, sbase, is_pp, row0, col0);

        float bsum = block_reduce(acc, red);
        if (tid == 0)
            atomicAdd(&g_acc[is_pp ? 0 : 2], (double)bsum);
    } else {
        // ---------------- edge stripe (fp32 exact) ----------------
        const int eb = bid - (N_PP_ACT + N_AP_T);
        float acc_pp = 0.f, acc_ap = 0.f;
        for (int e = eb * TPB + tid; e < E; e += N_EDGE_T * TPB) {
            {
                int s = e_pp[e];
                int t = e_pp[E + e];
                const float4* xs = reinterpret_cast<const float4*>(p_star + (size_t)s * DIM);
                const float4* yt = reinterpret_cast<const float4*>(p + (size_t)t * DIM);
                float d2 = 0.f;
                #pragma unroll
                for (int k = 0; k < 4; k++) {
                    float4 xv = xs[k], yv = yt[k];
                    float dx = xv.x - yv.x, dy = xv.y - yv.y;
                    float dz = xv.z - yv.z, dw = xv.w - yv.w;
                    d2 += dx*dx + dy*dy + dz*dz + dw*dw;
                }
                acc_pp += gamma[s] + gamma[t + N_PP] - fast_sqrt(d2);
            }
            {
                int s = e_ap[e];
                int t = e_ap[E + e];            // in [N_PP, 2*N_PP)
                const float4* xs = reinterpret_cast<const float4*>(p_star + (size_t)s * DIM);
                const float4* yt = reinterpret_cast<const float4*>(a + (size_t)(t - N_PP) * DIM);
                float d2 = 0.f;
                #pragma unroll
                for (int k = 0; k < 4; k++) {
                    float4 xv = xs[k], yv = yt[k];
                    float dx = xv.x - yv.x, dy = xv.y - yv.y;
                    float dz = xv.z - yv.z, dw = xv.w - yv.w;
                    d2 += dx*dx + dy*dy + dz*dz + dw*dw;
                }
                acc_ap += beta[s] + beta[t] - fast_sqrt(d2);
            }
        }
        float s_pp = block_reduce(acc_pp, red);
        __syncthreads();
        float s_ap = block_reduce(acc_ap, red);
        if (tid == 0) {
            atomicAdd(&g_acc[1], (double)s_pp);
            atomicAdd(&g_acc[3], (double)s_ap);
        }
    }

    // ---------------- arrival + finalize ----------------
    __syncthreads();
    if (tid == 0) {
        __threadfence();
        unsigned old = atomicAdd(&g_arrive, 1u);
        if (old == (unsigned)(NB_TOTAL - 1)) {
            double nll_pp = -(g_acc[1] - g_acc[0]);
            double nll_ap = -(g_acc[3] - g_acc[2]);
            out[0] = (float)(0.5 * nll_pp / (double)N_PP + 0.5 * nll_ap / (double)N_PP);
            g_acc[0] = 0.0; g_acc[1] = 0.0; g_acc[2] = 0.0; g_acc[3] = 0.0;
            g_arrive = 0u;
            __threadfence();
        }
    }
}

extern "C" void kernel_launch(void* const* d_in, const int* in_sizes, int n_in,
                              void* d_out, int out_size) {
    const float* p_star = (const float*)d_in[0];
    const float* p      = (const float*)d_in[1];
    const float* a      = (const float*)d_in[2];
    const float* beta   = (const float*)d_in[3];
    const float* gamma  = (const float*)d_in[4];
    const int*   e_pp   = (const int*)d_in[5];
    const int*   e_ap   = (const int*)d_in[6];
    int E = in_sizes[5] / 2;

    cudaFuncSetAttribute(fused_kernel,
                         cudaFuncAttributeMaxDynamicSharedMemorySize, SMEM_TOTAL);

    prep_kernel<<<96, 256>>>(p_star, p, a, beta, gamma);
    fused_kernel<<<NB_TOTAL, TPB, SMEM_TOTAL>>>(p_star, p, a, beta, gamma,
                                                e_pp, e_ap, E, (float*)d_out);
}